// round 10
// baseline (speedup 1.0000x reference)
#include <cuda_runtime.h>
#include <cuda_fp16.h>
#include <math.h>

#define B 64
#define J 2048
#define N 32
#define D 16
#define ND 512
#define EPS 1e-7f

// Swizzled fragment storage:
// g_Wsw[(j*64 + w*8 + nt)*32 + lane] = uint2{b0,b1} for r = 64w+8nt+gid, tig
__device__ __align__(16) uint2 g_Wsw[(size_t)J * 64 * 32];   // 33.5 MiB
// g_xsw[(j*8 + bh)*32 + lane] = uint2{a0,a2} for b = bh*8+gid, tig
__device__ __align__(16) uint2 g_xsw[(size_t)J * 8 * 32];    // 4.2 MiB
__device__ __align__(16) float g_spart[3][B * ND];           // s accum [b][n*16+d]

// ---- helpers --------------------------------------------------------------
static __device__ __forceinline__ unsigned long long pk2(float a, float b) {
    unsigned long long v;
    asm("mov.b64 %0, {%1, %2};" : "=l"(v) : "f"(a), "f"(b));
    return v;
}
static __device__ __forceinline__ float2 upk2(unsigned long long v) {
    float2 f;
    asm("mov.b64 {%0, %1}, %2;" : "=f"(f.x), "=f"(f.y) : "l"(v));
    return f;
}
static __device__ __forceinline__ void fma2(unsigned long long& d,
                                            unsigned long long a,
                                            unsigned long long b) {
    asm("fma.rn.f32x2 %0, %1, %2, %0;" : "+l"(d) : "l"(a), "l"(b));
}
static __device__ __forceinline__ void redv2(float* p, float a, float b) {
    asm volatile("red.global.add.v2.f32 [%0], {%1, %2};"
                 :: "l"(p), "f"(a), "f"(b) : "memory");
}
static __device__ __forceinline__ void mma16816(
    float& d0, float& d1, float& d2, float& d3,
    unsigned a0, unsigned a1, unsigned a2, unsigned a3,
    unsigned b0, unsigned b1,
    float c0, float c1, float c2, float c3) {
    asm volatile(
        "mma.sync.aligned.m16n8k16.row.col.f32.f16.f16.f32 "
        "{%0,%1,%2,%3},{%4,%5,%6,%7},{%8,%9},{%10,%11,%12,%13};"
        : "=f"(d0), "=f"(d1), "=f"(d2), "=f"(d3)
        : "r"(a0), "r"(a1), "r"(a2), "r"(a3), "r"(b0), "r"(b1),
          "f"(c0), "f"(c1), "f"(c2), "f"(c3));
}

// ---------------------------------------------------------------------------
__global__ void cvt_x_zero_kernel(const float* __restrict__ x) {
    int o = blockIdx.x * blockDim.x + threadIdx.x;  // < 524288
    const int lane = o & 31;
    const int bh = (o >> 5) & 7;
    const int j = o >> 8;
    const int tig = lane & 3;
    const int gid = lane >> 2;
    const int b = bh * 8 + gid;

    const float* xp = x + ((size_t)(b * J + j) << 4);
    float2 f0 = *reinterpret_cast<const float2*>(xp + 2 * tig);
    float2 f1 = *reinterpret_cast<const float2*>(xp + 2 * tig + 8);
    __half2 h0 = __floats2half2_rn(f0.x, f0.y);
    __half2 h1 = __floats2half2_rn(f1.x, f1.y);
    uint2 out;
    out.x = *reinterpret_cast<unsigned*>(&h0);
    out.y = *reinterpret_cast<unsigned*>(&h1);
    g_xsw[o] = out;

    if (o < 3 * B * ND) ((float*)g_spart)[o] = 0.0f;
}

// ---------------------------------------------------------------------------
// k_s0cvt: stream W fp32 -> fp16 swizzled fragments (coalesced store),
// mma-accumulate s0. grid 256 (jtile 8), 256 thr / 8 warps.
// ---------------------------------------------------------------------------
__global__ void __launch_bounds__(256, 1)
k_s0cvt_kernel(const float* __restrict__ Wf) {
    const int tid = threadIdx.x;
    const int w = tid >> 5;
    const int lane = tid & 31;
    const int gid = lane >> 2;
    const int tig = lane & 3;

    float C[8][4][4];
#pragma unroll
    for (int nt = 0; nt < 8; ++nt)
#pragma unroll
        for (int mi = 0; mi < 4; ++mi)
#pragma unroll
            for (int e = 0; e < 4; ++e) C[nt][mi][e] = 0.0f;

    for (int jj = 0; jj < 8; ++jj) {
        const int j = blockIdx.x * 8 + jj;

        float2 F0[8], F1[8];
#pragma unroll
        for (int nt = 0; nt < 8; ++nt) {
            const int r = 64 * w + 8 * nt + gid;
            const float* wp = Wf + ((size_t)((r >> 4) * J + j)) * 256 + ((r & 15) << 4);
            F0[nt] = *reinterpret_cast<const float2*>(wp + 2 * tig);
            F1[nt] = *reinterpret_cast<const float2*>(wp + 2 * tig + 8);
        }

        unsigned a[4][4];
#pragma unroll
        for (int mi = 0; mi < 4; ++mi) {
            uint2 xv0 = __ldg(&g_xsw[(size_t)(j * 8 + 2 * mi) * 32 + lane]);
            uint2 xv1 = __ldg(&g_xsw[(size_t)(j * 8 + 2 * mi + 1) * 32 + lane]);
            a[mi][0] = xv0.x;
            a[mi][1] = xv1.x;
            a[mi][2] = xv0.y;
            a[mi][3] = xv1.y;
        }

#pragma unroll
        for (int nt = 0; nt < 8; ++nt) {
            __half2 h0 = __floats2half2_rn(F0[nt].x, F0[nt].y);
            __half2 h1 = __floats2half2_rn(F1[nt].x, F1[nt].y);
            unsigned b0 = *reinterpret_cast<unsigned*>(&h0);
            unsigned b1 = *reinterpret_cast<unsigned*>(&h1);
            uint2 wout; wout.x = b0; wout.y = b1;
            g_Wsw[(size_t)(j * 64 + w * 8 + nt) * 32 + lane] = wout;
#pragma unroll
            for (int mi = 0; mi < 4; ++mi)
                mma16816(C[nt][mi][0], C[nt][mi][1], C[nt][mi][2], C[nt][mi][3],
                         a[mi][0], a[mi][1], a[mi][2], a[mi][3], b0, b1,
                         C[nt][mi][0], C[nt][mi][1], C[nt][mi][2], C[nt][mi][3]);
        }
    }

#pragma unroll
    for (int nt = 0; nt < 8; ++nt) {
        const int r = 64 * w + 8 * nt + 2 * tig;
#pragma unroll
        for (int mi = 0; mi < 4; ++mi) {
            const int brow = mi * 16 + gid;
            redv2(&g_spart[0][brow * ND + r], C[nt][mi][0], C[nt][mi][1]);
            redv2(&g_spart[0][(brow + 8) * ND + r], C[nt][mi][2], C[nt][mi][3]);
        }
    }
}

// ---------------------------------------------------------------------------
// Fused routing pass, 16-b blocks (full mma tiles), 2 CTAs/SM at 128 regs.
// grid 296: bg = blockIdx.x & 3 (16 b), cid = blockIdx.x >> 2 (j chunk 28/26).
// Pipeline per round: CONSUME(j-1) -> PRODUCE(j) -> LOADWX(j+1) -> bar.
// MODE 1: v = squash(s0/32); MODE 2: v = squash(s0/32)+squash(s1).
// ---------------------------------------------------------------------------
template <int MODE>
__global__ void __launch_bounds__(256, 2) route_fused_kernel() {
    __shared__ float ts[2][16][36];

    const int tid = threadIdx.x;
    const int w = tid >> 5;
    const int lane = tid & 31;
    const int gid = lane >> 2;
    const int tig = lane & 3;
    const int bg = blockIdx.x & 3;
    const int cid = blockIdx.x >> 2;  // 0..73

    int jstart, rounds;
    if (cid < 62) { jstart = 28 * cid; rounds = 28; }
    else { jstart = 1736 + 26 * (cid - 62); rounds = 26; }

    const int b0 = bg * 16;

    // --- prologue: squash(s) -> v in registers -----------------------------
    unsigned long long vr[2][4][2];
#pragma unroll
    for (int bi = 0; bi < 2; ++bi) {
#pragma unroll
        for (int q = 0; q < 4; ++q) {
            const int b = b0 + gid + 8 * bi;
            const int n = 4 * w + q;
            float vx0 = 0.f, vy0 = 0.f, vx1 = 0.f, vy1 = 0.f;
#pragma unroll
            for (int it = 0; it < MODE; ++it) {
                const float pre = (it == 0) ? (1.0f / 32.0f) : 1.0f;
                const float* sp = &g_spart[it][(b * 32 + n) * 16];
                float2 f0 = *reinterpret_cast<const float2*>(sp + 2 * tig);
                float2 f1 = *reinterpret_cast<const float2*>(sp + 8 + 2 * tig);
                f0.x *= pre; f0.y *= pre; f1.x *= pre; f1.y *= pre;
                float p = f0.x * f0.x + f0.y * f0.y + f1.x * f1.x + f1.y * f1.y;
                p += __shfl_xor_sync(0xffffffffu, p, 1);
                p += __shfl_xor_sync(0xffffffffu, p, 2);
                p += EPS;
                float sc = sqrtf(p) / (1.0f + p);
                vx0 += sc * f0.x; vy0 += sc * f0.y;
                vx1 += sc * f1.x; vy1 += sc * f1.y;
            }
            vr[bi][q][0] = pk2(vx0, vy0);
            vr[bi][q][1] = pk2(vx1, vy1);
        }
    }

    unsigned long long s2[8][2];
#pragma unroll
    for (int nt = 0; nt < 8; ++nt) { s2[nt][0] = 0ull; s2[nt][1] = 0ull; }

    unsigned W0[8], W1[8];
    unsigned a0r, a1r, a2r, a3r;
    unsigned long long p01[8], p23[8];

    // incremental pointers
    const uint2* wb = g_Wsw + (size_t)(jstart * 64 + w * 8) * 32 + lane;
    const uint2* xp = g_xsw + (size_t)(jstart * 8 + 2 * bg) * 32 + lane;

#define LOADWX()                                                               \
    {                                                                          \
        uint2 xv0 = __ldg(xp);                                                 \
        uint2 xv1 = __ldg(xp + 32);                                            \
        a0r = xv0.x; a1r = xv1.x; a2r = xv0.y; a3r = xv1.y;                    \
        _Pragma("unroll") for (int nt = 0; nt < 8; ++nt) {                     \
            uint2 wv = __ldg(wb + nt * 32);                                    \
            W0[nt] = wv.x;                                                     \
            W1[nt] = wv.y;                                                     \
        }                                                                      \
        wb += 64 * 32;                                                         \
        xp += 8 * 32;                                                          \
    }

#define PRODUCE(par)                                                           \
    {                                                                          \
        _Pragma("unroll") for (int nt = 0; nt < 8; ++nt) {                     \
            float d0, d1, d2, d3;                                              \
            mma16816(d0, d1, d2, d3, a0r, a1r, a2r, a3r, W0[nt], W1[nt],       \
                     0.0f, 0.0f, 0.0f, 0.0f);                                  \
            p01[nt] = pk2(d0, d1);                                             \
            p23[nt] = pk2(d2, d3);                                             \
        }                                                                      \
        float tv0[4], tv1[4];                                                  \
        _Pragma("unroll") for (int q = 0; q < 4; ++q) {                        \
            unsigned long long t2 = 0ull;                                      \
            fma2(t2, p01[2 * q], vr[0][q][0]);                                 \
            fma2(t2, p01[2 * q + 1], vr[0][q][1]);                             \
            float2 f = upk2(t2);                                               \
            float tt = f.x + f.y;                                              \
            tt += __shfl_xor_sync(0xffffffffu, tt, 1);                         \
            tt += __shfl_xor_sync(0xffffffffu, tt, 2);                         \
            tv0[q] = tt;                                                       \
            unsigned long long u2 = 0ull;                                      \
            fma2(u2, p23[2 * q], vr[1][q][0]);                                 \
            fma2(u2, p23[2 * q + 1], vr[1][q][1]);                             \
            float2 g = upk2(u2);                                               \
            float uu = g.x + g.y;                                              \
            uu += __shfl_xor_sync(0xffffffffu, uu, 1);                         \
            uu += __shfl_xor_sync(0xffffffffu, uu, 2);                         \
            tv1[q] = uu;                                                       \
        }                                                                      \
        float e0 = __expf(tig == 0 ? tv0[0] : tig == 1 ? tv0[1]                \
                                  : tig == 2 ? tv0[2] : tv0[3]);               \
        float e1 = __expf(tig == 0 ? tv1[0] : tig == 1 ? tv1[1]                \
                                  : tig == 2 ? tv1[2] : tv1[3]);               \
        ts[par][gid][4 * w + tig] = e0;                                        \
        ts[par][gid + 8][4 * w + tig] = e1;                                    \
    }

#define CONSUME(par)                                                           \
    {                                                                          \
        float4 sa0 = *reinterpret_cast<const float4*>(&ts[par][gid][tig * 8]); \
        float4 sa1 = *reinterpret_cast<const float4*>(&ts[par][gid][tig * 8 + 4]);\
        float4 sb0 = *reinterpret_cast<const float4*>(&ts[par][gid + 8][tig * 8]);\
        float4 sb1 = *reinterpret_cast<const float4*>(&ts[par][gid + 8][tig * 8 + 4]);\
        float SA = sa0.x + sa0.y + sa0.z + sa0.w + sa1.x + sa1.y + sa1.z + sa1.w;\
        float SB = sb0.x + sb0.y + sb0.z + sb0.w + sb1.x + sb1.y + sb1.z + sb1.w;\
        SA += __shfl_xor_sync(0xffffffffu, SA, 1);                             \
        SA += __shfl_xor_sync(0xffffffffu, SA, 2);                             \
        SB += __shfl_xor_sync(0xffffffffu, SB, 1);                             \
        SB += __shfl_xor_sync(0xffffffffu, SB, 2);                             \
        float rA = __fdividef(1.0f, SA);                                       \
        float rB = __fdividef(1.0f, SB);                                       \
        float4 eA = *reinterpret_cast<const float4*>(&ts[par][gid][4 * w]);    \
        float4 eB = *reinterpret_cast<const float4*>(&ts[par][gid + 8][4 * w]);\
        const float cAa[4] = {eA.x * rA, eA.y * rA, eA.z * rA, eA.w * rA};     \
        const float cBa[4] = {eB.x * rB, eB.y * rB, eB.z * rB, eB.w * rB};     \
        _Pragma("unroll") for (int nt = 0; nt < 8; ++nt) {                     \
            const int q = nt >> 1;                                             \
            fma2(s2[nt][0], pk2(cAa[q], cAa[q]), p01[nt]);                     \
            fma2(s2[nt][1], pk2(cBa[q], cBa[q]), p23[nt]);                     \
        }                                                                      \
    }

    // prologue of pipeline
    LOADWX();                 // loads j0
    PRODUCE(0);               // produce j0 (ts[0])
    LOADWX();                 // loads j1 (in flight over the barrier)
    __syncthreads();
    for (int rd = 1; rd < rounds; ++rd) {
        const int par = rd & 1;
        CONSUME(par ^ 1);     // consume j_{rd-1} (p01/p23 still hold it)
        PRODUCE(par);         // produce j_rd (overwrites p01/p23, writes ts[par])
        if (rd + 1 < rounds) LOADWX();  // issue loads for j_{rd+1}
        __syncthreads();
    }
    CONSUME((rounds - 1) & 1);
#undef PRODUCE
#undef CONSUME
#undef LOADWX

    // flush s partials
#pragma unroll
    for (int nt = 0; nt < 8; ++nt) {
        const int r = 64 * w + 8 * nt + 2 * tig;
        float2 fa = upk2(s2[nt][0]);
        float2 fb = upk2(s2[nt][1]);
        redv2(&g_spart[MODE][(b0 + gid) * ND + r], fa.x, fa.y);
        redv2(&g_spart[MODE][(b0 + gid + 8) * ND + r], fb.x, fb.y);
    }
}

// ---------------------------------------------------------------------------
__global__ void squash_out_kernel(float* __restrict__ out) {
    int t = blockIdx.x * blockDim.x + threadIdx.x;  // (b*32+n)
    const float* s = &g_spart[2][t * 16];
    float sv[16];
    float s2 = 0.0f;
#pragma unroll
    for (int d = 0; d < 16; ++d) {
        float val = s[d];
        sv[d] = val;
        s2 = fmaf(val, val, s2);
    }
    s2 += EPS;
    float sc = sqrtf(s2) / (1.0f + s2);
#pragma unroll
    for (int d = 0; d < 16; ++d) out[t * 16 + d] = sc * sv[d];
}

// ---------------------------------------------------------------------------
extern "C" void kernel_launch(void* const* d_in, const int* in_sizes, int n_in,
                              void* d_out, int out_size) {
    const float* x = (const float*)d_in[0];  // [B, J, 16]
    const float* W = (const float*)d_in[1];  // [N, J, D, 16]
    float* out = (float*)d_out;              // [B, N, D]

    cvt_x_zero_kernel<<<2048, 256>>>(x);
    k_s0cvt_kernel<<<256, 256>>>(W);
    route_fused_kernel<1><<<296, 256>>>();
    route_fused_kernel<2><<<296, 256>>>();
    squash_out_kernel<<<16, 128>>>(out);
}